// round 7
// baseline (speedup 1.0000x reference)
#include <cuda_runtime.h>
#include <math.h>
#include <stdint.h>

// Shapes (fixed by the problem)
constexpr int B  = 4;
constexpr int NQ = 128;
constexpr int S  = 16384;
constexpr int E  = 256;
constexpr int H  = 8;
constexpr int DH = 32;

constexpr int SPLITS = 16;
constexpr int SCHUNK = S / SPLITS;   // 1024
constexpr int SKT    = 64;           // kv tile per inner iteration
constexpr int NT     = SCHUNK / SKT; // 16
constexpr int SW     = S / 32;       // 512 mask words per row

constexpr float NEG = -1e30f;

#define DEV_INLINE __device__ __forceinline__

// ---------------- scratch (static device memory; no allocations) ----------------
__device__ float    g_q[B * NQ * E];
__device__ float    g_k[(size_t)B * S * E];
__device__ float    g_v[(size_t)B * S * E];
__device__ float    g_attn[B * NQ * E];
__device__ float    g_po[(size_t)B * H * SPLITS * NQ * DH];
__device__ float    g_pm[B * H * SPLITS * NQ];
__device__ float    g_pl[B * H * SPLITS * NQ];
__device__ uint32_t g_mbits[(size_t)B * NQ * SW];   // bit=1 => masked (disallowed)

// ---------------- helpers ----------------
DEV_INLINE uint32_t f2tf(float x) {
    uint32_t u;
    asm("cvt.rna.tf32.f32 %0, %1;" : "=r"(u) : "f"(x));
    return u;
}
DEV_INLINE uint32_t raw2tf(uint32_t r) { return f2tf(__uint_as_float(r)); }

DEV_INLINE void mma8(float* d, const uint32_t* a, uint32_t b0, uint32_t b1) {
    asm volatile(
        "mma.sync.aligned.m16n8k8.row.col.f32.tf32.tf32.f32 "
        "{%0,%1,%2,%3}, {%4,%5,%6,%7}, {%8,%9}, {%0,%1,%2,%3};\n"
        : "+f"(d[0]), "+f"(d[1]), "+f"(d[2]), "+f"(d[3])
        : "r"(a[0]), "r"(a[1]), "r"(a[2]), "r"(a[3]), "r"(b0), "r"(b1));
}

// ldmatrix x4 on f32 data via the b16-pair trick: 8x8 b16 tile == 8 rows x 4 f32
// cols; thread t of each octet gets f32 element (row t/4, col t%4).
DEV_INLINE void ldsm4(uint32_t& r0, uint32_t& r1, uint32_t& r2, uint32_t& r3,
                      uint32_t addr) {
    asm volatile("ldmatrix.sync.aligned.m8n8.x4.shared.b16 {%0,%1,%2,%3}, [%4];"
                 : "=r"(r0), "=r"(r1), "=r"(r2), "=r"(r3) : "r"(addr));
}

DEV_INLINE void cp16(uint32_t smem_addr, const void* gptr) {
    asm volatile("cp.async.cg.shared.global [%0], [%1], 16;\n"
                 :: "r"(smem_addr), "l"(gptr));
}
DEV_INLINE void cp_commit() { asm volatile("cp.async.commit_group;\n"); }
template <int N> DEV_INLINE void cp_wait() {
    asm volatile("cp.async.wait_group %0;\n" :: "n"(N));
}

// ---------------- kernel 0: pack mask into bits ----------------
// bit=1 => masked. Fully-masked rows are written as all-zero (reference resets them).
__global__ __launch_bounds__(256)
void maskpack_kernel(const float* __restrict__ mask) {
    int row = blockIdx.x;                 // 0 .. B*NQ-1
    __shared__ uint32_t wbuf[SW];
    __shared__ int s_all;
    int tid = threadIdx.x, warp = tid >> 5, lane = tid & 31;
    if (tid == 0) s_all = 1;
    __syncthreads();
    const float* mp = mask + (size_t)row * S;
    int myall = 1;
    constexpr int WPW = SW / 8;           // 64 words per warp
    for (int i = 0; i < WPW; i++) {
        int word = warp * WPW + i;
        float v = mp[word * 32 + lane];
        uint32_t bits = __ballot_sync(0xffffffffu, v < 0.5f);
        if (lane == 0) wbuf[word] = bits;
        myall &= (bits == 0xffffffffu);
    }
    if (!myall) s_all = 0;                // benign race
    __syncthreads();
    uint32_t* out = g_mbits + (size_t)row * SW;
    int all = s_all;
    for (int w = tid; w < SW; w += blockDim.x) out[w] = all ? 0u : wbuf[w];
}

// ---------------- TF32 GEMM: C[M,256] = alpha*(A @ W^T + bias) ----------------
// BM=128, BN=128, BK=32, 2-stage cp.async, ldmatrix fragments.
// 256 threads = 8 warps, 4(m) x 2(n), warp tile 32x64.
constexpr int AST = 36;                               // smem row stride (floats)
constexpr int GEMM_SMEM_BYTES = 2 * (128 + 128) * AST * 4;   // 73728
constexpr int NKT = E / 32;                           // 8 k-tiles

__global__ __launch_bounds__(256, 2)
void gemm_tf32_kernel(const float* __restrict__ A, const float* __restrict__ W,
                      const float* __restrict__ bias, float* __restrict__ C,
                      float alpha) {
    extern __shared__ float smem[];
    const int tid = threadIdx.x, warp = tid >> 5, lane = tid & 31;
    const int wm = warp >> 1, wn = warp & 1;
    const int m0 = blockIdx.x * 128, n0 = blockIdx.y * 128;
    const int mnum = lane >> 3, rinm = lane & 7;

    // ldmatrix lane geometry
    const int a_row0 = wm * 32 + (mnum & 1) * 8 + rinm;   // + mt*16
    const int a_colb = (mnum >> 1) * 4;
    const int b_row0 = wn * 64 + (mnum >> 1) * 8 + rinm;  // + p*16
    const int b_colb = (mnum & 1) * 4;

    const uint32_t sbase = (uint32_t)__cvta_generic_to_shared(smem);
    constexpr uint32_t STAGE = (128 + 128) * AST * 4;

    float acc[2][8][4];
#pragma unroll
    for (int a = 0; a < 2; a++)
#pragma unroll
        for (int b = 0; b < 8; b++)
#pragma unroll
            for (int c = 0; c < 4; c++) acc[a][b][c] = 0.f;

    auto load_stage = [&](int kt, int s) {
        const float* Ab = A + (size_t)m0 * E + kt * 32;
        const float* Wb = W + (size_t)n0 * E + kt * 32;
        uint32_t as = sbase + s * STAGE;
        uint32_t ws = as + 128 * AST * 4;
#pragma unroll
        for (int i = 0; i < 4; i++) {                 // A: 128x32 = 1024 float4
            int idx = i * 256 + tid;
            int r = idx >> 3, c = (idx & 7) * 4;
            cp16(as + (r * AST + c) * 4, Ab + (size_t)r * E + c);
        }
#pragma unroll
        for (int i = 0; i < 4; i++) {                 // W: 128x32 = 1024 float4
            int idx = i * 256 + tid;
            int r = idx >> 3, c = (idx & 7) * 4;
            cp16(ws + (r * AST + c) * 4, Wb + (size_t)r * E + c);
        }
    };

    load_stage(0, 0); cp_commit();

    for (int kt = 0; kt < NKT; kt++) {
        if (kt + 1 < NKT) { load_stage(kt + 1, (kt + 1) & 1); cp_commit(); cp_wait<1>(); }
        else              { cp_wait<0>(); }
        __syncthreads();

        uint32_t as = sbase + (kt & 1) * STAGE;
        uint32_t ws = as + 128 * AST * 4;
#pragma unroll
        for (int kk = 0; kk < 4; kk++) {
            const int k8 = kk * 8;
            uint32_t a[2][4], bf[4][4];
#pragma unroll
            for (int mt = 0; mt < 2; mt++)
                ldsm4(a[mt][0], a[mt][1], a[mt][2], a[mt][3],
                      as + ((a_row0 + mt * 16) * AST + k8 + a_colb) * 4);
#pragma unroll
            for (int p = 0; p < 4; p++)
                ldsm4(bf[p][0], bf[p][1], bf[p][2], bf[p][3],
                      ws + ((b_row0 + p * 16) * AST + k8 + b_colb) * 4);
#pragma unroll
            for (int mt = 0; mt < 2; mt++)
#pragma unroll
                for (int j = 0; j < 4; j++) a[mt][j] = raw2tf(a[mt][j]);
#pragma unroll
            for (int p = 0; p < 4; p++)
#pragma unroll
                for (int j = 0; j < 4; j++) bf[p][j] = raw2tf(bf[p][j]);
#pragma unroll
            for (int mt = 0; mt < 2; mt++)
#pragma unroll
                for (int p = 0; p < 4; p++) {
                    mma8(acc[mt][2 * p],     a[mt], bf[p][0], bf[p][1]);
                    mma8(acc[mt][2 * p + 1], a[mt], bf[p][2], bf[p][3]);
                }
        }
        __syncthreads();
    }

    // epilogue
    const int g = lane >> 2, tg = lane & 3;
#pragma unroll
    for (int mt = 0; mt < 2; mt++) {
        int r = m0 + wm * 32 + mt * 16 + g;
#pragma unroll
        for (int nt = 0; nt < 8; nt++) {
            int c = n0 + wn * 64 + nt * 8 + 2 * tg;
            float b0v = bias[c], b1v = bias[c + 1];
            float2 o0 = make_float2(alpha * (acc[mt][nt][0] + b0v),
                                    alpha * (acc[mt][nt][1] + b1v));
            float2 o1 = make_float2(alpha * (acc[mt][nt][2] + b0v),
                                    alpha * (acc[mt][nt][3] + b1v));
            *(float2*)(C + (size_t)r * E + c)       = o0;
            *(float2*)(C + (size_t)(r + 8) * E + c) = o1;
        }
    }
}

// ---------------- attention kernel (flash-style, split over S) ----------------
// (exact version that passed at 331.8us in Round 4)
constexpr int KST = 36, VST = 40, PST = 68;
constexpr int ATTN_SMEM_BYTES = (2 * SKT * KST + 2 * SKT * VST + NQ * PST) * 4;

__global__ __launch_bounds__(256)
void attn_kernel() {
    extern __shared__ float smem[];
    float* Vbuf = smem + 2 * SKT * KST;
    float* Ps   = Vbuf + 2 * SKT * VST;

    const int split = blockIdx.x, h = blockIdx.y, b = blockIdx.z;
    const int tid = threadIdx.x, warp = tid >> 5, lane = tid & 31;
    const int g = lane >> 2, tg = lane & 3;
    const int mnum = lane >> 3, rinm = lane & 7;

    const uint32_t sbase = (uint32_t)__cvta_generic_to_shared(smem);
    const uint32_t kba = sbase;
    const uint32_t vba = sbase + 2 * SKT * KST * 4;
    const uint32_t pba = vba + 2 * SKT * VST * 4;

    const int r0 = warp * 16 + g, r1 = r0 + 8;

    // hoist Q fragments into registers (loop-invariant)
    uint32_t qf[4][4];
    {
        const float* q0 = g_q + (size_t)(b * NQ + r0) * E + h * DH;
        const float* q1 = g_q + (size_t)(b * NQ + r1) * E + h * DH;
#pragma unroll
        for (int kk = 0; kk < 4; kk++) {
            qf[kk][0] = f2tf(q0[kk * 8 + tg]);
            qf[kk][1] = f2tf(q1[kk * 8 + tg]);
            qf[kk][2] = f2tf(q0[kk * 8 + tg + 4]);
            qf[kk][3] = f2tf(q1[kk * 8 + tg + 4]);
        }
    }

    const uint32_t* mw0 = g_mbits + (size_t)(b * NQ + r0) * SW;
    const uint32_t* mw1 = g_mbits + (size_t)(b * NQ + r1) * SW;
    const float* kbase = g_k + (size_t)b * S * E + h * DH;
    const float* vbase = g_v + (size_t)b * S * E + h * DH;
    const int sstart = split * SCHUNK;

    // ldmatrix geometry
    const int k_row  = (mnum >> 1) * 8 + rinm;            // + p*16 (K as B operand)
    const int k_colb = (mnum & 1) * 4;
    const int p_row  = warp * 16 + (mnum & 1) * 8 + rinm; // P as A operand
    const int p_colb = (mnum >> 1) * 4;

    float m0v = NEG, m1v = NEG, l0 = 0.f, l1 = 0.f;
    float o[4][4];
#pragma unroll
    for (int i = 0; i < 4; i++)
#pragma unroll
        for (int j = 0; j < 4; j++) o[i][j] = 0.f;

    auto load_kv = [&](int t, int s) {
        const float* kb = kbase + (size_t)(sstart + t * SKT) * E;
        const float* vb = vbase + (size_t)(sstart + t * SKT) * E;
        uint32_t ka = kba + s * SKT * KST * 4;
        uint32_t va = vba + s * SKT * VST * 4;
#pragma unroll
        for (int i = 0; i < 2; i++) {             // 64x32 = 512 float4 each
            int idx = i * 256 + tid;
            int r = idx >> 3, c = (idx & 7) * 4;
            cp16(ka + (r * KST + c) * 4, kb + (size_t)r * E + c);
            cp16(va + (r * VST + c) * 4, vb + (size_t)r * E + c);
        }
    };

    load_kv(0, 0); cp_commit();

    for (int t = 0; t < NT; t++) {
        if (t + 1 < NT) { load_kv(t + 1, (t + 1) & 1); cp_commit(); cp_wait<1>(); }
        else            { cp_wait<0>(); }
        __syncthreads();

        const int s0 = sstart + t * SKT;
        const uint32_t ka = kba + (t & 1) * SKT * KST * 4;
        const float* Vp = Vbuf + (t & 1) * SKT * VST;

        // scores S_tile[16 x 64] per warp
        float sc[8][4];
#pragma unroll
        for (int n = 0; n < 8; n++)
#pragma unroll
            for (int j = 0; j < 4; j++) sc[n][j] = 0.f;

#pragma unroll
        for (int kk = 0; kk < 4; kk++) {
            const int k8 = kk * 8;
#pragma unroll
            for (int p = 0; p < 4; p++) {
                uint32_t br[4];
                ldsm4(br[0], br[1], br[2], br[3],
                      ka + ((k_row + p * 16) * KST + k8 + k_colb) * 4);
#pragma unroll
                for (int j = 0; j < 4; j++) br[j] = raw2tf(br[j]);
                mma8(sc[2 * p],     qf[kk], br[0], br[1]);
                mma8(sc[2 * p + 1], qf[kk], br[2], br[3]);
            }
        }

        // mask (bit=1 => disallowed) + row max
        uint2 w0 = *(const uint2*)(mw0 + (s0 >> 5));
        uint2 w1 = *(const uint2*)(mw1 + (s0 >> 5));
        uint64_t bm0 = (uint64_t)w0.x | ((uint64_t)w0.y << 32);
        uint64_t bm1 = (uint64_t)w1.x | ((uint64_t)w1.y << 32);

        float tm0 = NEG, tm1 = NEG;
#pragma unroll
        for (int n = 0; n < 8; n++) {
            int c = n * 8 + 2 * tg;
            if ((bm0 >> c) & 1)       sc[n][0] = NEG;
            if ((bm0 >> (c + 1)) & 1) sc[n][1] = NEG;
            if ((bm1 >> c) & 1)       sc[n][2] = NEG;
            if ((bm1 >> (c + 1)) & 1) sc[n][3] = NEG;
            tm0 = fmaxf(tm0, fmaxf(sc[n][0], sc[n][1]));
            tm1 = fmaxf(tm1, fmaxf(sc[n][2], sc[n][3]));
        }
        tm0 = fmaxf(tm0, __shfl_xor_sync(0xffffffffu, tm0, 1));
        tm0 = fmaxf(tm0, __shfl_xor_sync(0xffffffffu, tm0, 2));
        tm1 = fmaxf(tm1, __shfl_xor_sync(0xffffffffu, tm1, 1));
        tm1 = fmaxf(tm1, __shfl_xor_sync(0xffffffffu, tm1, 2));

        float mn0 = fmaxf(m0v, tm0), mn1 = fmaxf(m1v, tm1);
        float cf0 = __expf(m0v - mn0), cf1 = __expf(m1v - mn1);

        float rs0 = 0.f, rs1 = 0.f;
#pragma unroll
        for (int n = 0; n < 8; n++) {
            float p0 = __expf(sc[n][0] - mn0);
            float p1 = __expf(sc[n][1] - mn0);
            float p2 = __expf(sc[n][2] - mn1);
            float p3 = __expf(sc[n][3] - mn1);
            rs0 += p0 + p1;
            rs1 += p2 + p3;
            int c = n * 8 + 2 * tg;
            Ps[r0 * PST + c]     = __uint_as_float(f2tf(p0));
            Ps[r0 * PST + c + 1] = __uint_as_float(f2tf(p1));
            Ps[r1 * PST + c]     = __uint_as_float(f2tf(p2));
            Ps[r1 * PST + c + 1] = __uint_as_float(f2tf(p3));
        }
        rs0 += __shfl_xor_sync(0xffffffffu, rs0, 1);
        rs0 += __shfl_xor_sync(0xffffffffu, rs0, 2);
        rs1 += __shfl_xor_sync(0xffffffffu, rs1, 1);
        rs1 += __shfl_xor_sync(0xffffffffu, rs1, 2);

        l0 = l0 * cf0 + rs0;
        l1 = l1 * cf1 + rs1;
        m0v = mn0; m1v = mn1;
#pragma unroll
        for (int nt = 0; nt < 4; nt++) {
            o[nt][0] *= cf0; o[nt][1] *= cf0;
            o[nt][2] *= cf1; o[nt][3] *= cf1;
        }
        __syncwarp();

        // O += P[16 x 64] @ V[64 x 32]
#pragma unroll
        for (int kk = 0; kk < 8; kk++) {
            const int k8 = kk * 8;
            uint32_t pa[4];
            ldsm4(pa[0], pa[1], pa[2], pa[3],
                  pba + (p_row * PST + k8 + p_colb) * 4);   // already tf32
#pragma unroll
            for (int nt = 0; nt < 4; nt++) {
                uint32_t b0 = f2tf(Vp[(k8 + tg) * VST + nt * 8 + g]);
                uint32_t b1 = f2tf(Vp[(k8 + tg + 4) * VST + nt * 8 + g]);
                mma8(o[nt], pa, b0, b1);
            }
        }
        __syncwarp();
        __syncthreads();   // before K/V buffers are overwritten
    }

    // write partials (unnormalized)
    size_t pbase = (size_t)((b * H + h) * SPLITS + split) * NQ;
#pragma unroll
    for (int nt = 0; nt < 4; nt++) {
        int c = nt * 8 + 2 * tg;
        *(float2*)(g_po + (pbase + r0) * DH + c) = make_float2(o[nt][0], o[nt][1]);
        *(float2*)(g_po + (pbase + r1) * DH + c) = make_float2(o[nt][2], o[nt][3]);
    }
    if (tg == 0) {
        g_pm[pbase + r0] = m0v; g_pl[pbase + r0] = l0;
        g_pm[pbase + r1] = m1v; g_pl[pbase + r1] = l1;
    }
}

// ---------------- combine kernel ----------------
__global__ __launch_bounds__(256)
void combine_kernel() {
    int widx = blockIdx.x * (blockDim.x >> 5) + (threadIdx.x >> 5);
    int lane = threadIdx.x & 31;
    if (widx >= B * H * NQ) return;
    int q = widx % NQ;
    int bh = widx / NQ;
    int h = bh % H, b = bh / H;

    size_t base = (size_t)bh * SPLITS * NQ + q;
    float M = NEG;
#pragma unroll
    for (int i = 0; i < SPLITS; i++) M = fmaxf(M, g_pm[base + (size_t)i * NQ]);
    float L = 0.f, acc = 0.f;
#pragma unroll
    for (int i = 0; i < SPLITS; i++) {
        float w = __expf(g_pm[base + (size_t)i * NQ] - M);
        L += w * g_pl[base + (size_t)i * NQ];
        acc += w * g_po[(base + (size_t)i * NQ) * DH + lane];
    }
    g_attn[(size_t)(b * NQ + q) * E + h * DH + lane] = acc / L;
}

// ---------------- launcher ----------------
extern "C" void kernel_launch(void* const* d_in, const int* in_sizes, int n_in,
                              void* d_out, int out_size) {
    const float* query = (const float*)d_in[0];
    const float* key   = (const float*)d_in[1];
    const float* value = (const float*)d_in[2];
    const float* mask  = (const float*)d_in[3];
    const float* W_in  = (const float*)d_in[4];
    const float* b_in  = (const float*)d_in[5];
    const float* W_out = (const float*)d_in[6];
    const float* b_out = (const float*)d_in[7];
    float* out = (float*)d_out;

    float *p_q, *p_k, *p_v, *p_attn;
    cudaGetSymbolAddress((void**)&p_q, g_q);
    cudaGetSymbolAddress((void**)&p_k, g_k);
    cudaGetSymbolAddress((void**)&p_v, g_v);
    cudaGetSymbolAddress((void**)&p_attn, g_attn);

    cudaFuncSetAttribute(gemm_tf32_kernel, cudaFuncAttributeMaxDynamicSharedMemorySize,
                         GEMM_SMEM_BYTES);
    cudaFuncSetAttribute(attn_kernel, cudaFuncAttributeMaxDynamicSharedMemorySize,
                         ATTN_SMEM_BYTES);

    const float qscale = 1.0f / sqrtf((float)DH);

    // 0) pack mask bits (handles fully-masked-row reset)
    maskpack_kernel<<<B * NQ, 256>>>(mask);

    // 1) Q projection (scaled)
    gemm_tf32_kernel<<<dim3((B * NQ) / 128, E / 128), 256, GEMM_SMEM_BYTES>>>(
        query, W_in, b_in, p_q, qscale);

    // 2) K projection
    gemm_tf32_kernel<<<dim3((B * S) / 128, E / 128), 256, GEMM_SMEM_BYTES>>>(
        key, W_in + E * E, b_in + E, p_k, 1.0f);

    // 3) V projection
    gemm_tf32_kernel<<<dim3((B * S) / 128, E / 128), 256, GEMM_SMEM_BYTES>>>(
        value, W_in + 2 * E * E, b_in + 2 * E, p_v, 1.0f);

    // 4) attention (split over S)
    attn_kernel<<<dim3(SPLITS, H, B), 256, ATTN_SMEM_BYTES>>>();

    // 5) combine splits
    combine_kernel<<<(B * H * NQ + 7) / 8, 256>>>();

    // 6) output projection
    gemm_tf32_kernel<<<dim3((B * NQ) / 128, E / 128), 256, GEMM_SMEM_BYTES>>>(
        p_attn, W_out, b_out, out, 1.0f);
}

// round 10
// speedup vs baseline: 1.1397x; 1.1397x over previous
#include <cuda_runtime.h>
#include <math.h>
#include <stdint.h>

// Shapes (fixed by the problem)
constexpr int B  = 4;
constexpr int NQ = 128;
constexpr int S  = 16384;
constexpr int E  = 256;
constexpr int H  = 8;
constexpr int DH = 32;

constexpr int SPLITS = 16;
constexpr int SCHUNK = S / SPLITS;   // 1024
constexpr int SKT    = 64;           // kv tile per inner iteration
constexpr int NT     = SCHUNK / SKT; // 16
constexpr int SW     = S / 32;       // 512 mask words per row

constexpr float NEG = -1e30f;

#define DEV_INLINE __device__ __forceinline__

// ---------------- scratch (static device memory; no allocations) ----------------
__device__ float    g_q[B * NQ * E];                 // projected Q (scaled, f32)
__device__ float    g_k[(size_t)B * S * E];          // projected K (tf32-rounded f32)
__device__ float    g_v[(size_t)B * S * E];          // projected V (tf32-rounded f32)
__device__ float    g_attn[B * NQ * E];
__device__ float    g_po[(size_t)B * H * SPLITS * NQ * DH];
__device__ float    g_pm[B * H * SPLITS * NQ];
__device__ float    g_pl[B * H * SPLITS * NQ];
__device__ uint32_t g_mbits[(size_t)B * NQ * SW];    // bit=1 => masked (disallowed)

// ---------------- helpers ----------------
DEV_INLINE uint32_t f2tf(float x) {
    uint32_t u;
    asm("cvt.rna.tf32.f32 %0, %1;" : "=r"(u) : "f"(x));
    return u;
}
DEV_INLINE float f2tff(float x) { return __uint_as_float(f2tf(x)); }
DEV_INLINE uint32_t raw2tf(uint32_t r) { return f2tf(__uint_as_float(r)); }

DEV_INLINE void mma8(float* d, const uint32_t* a, uint32_t b0, uint32_t b1) {
    asm volatile(
        "mma.sync.aligned.m16n8k8.row.col.f32.tf32.tf32.f32 "
        "{%0,%1,%2,%3}, {%4,%5,%6,%7}, {%8,%9}, {%0,%1,%2,%3};\n"
        : "+f"(d[0]), "+f"(d[1]), "+f"(d[2]), "+f"(d[3])
        : "r"(a[0]), "r"(a[1]), "r"(a[2]), "r"(a[3]), "r"(b0), "r"(b1));
}

// ldmatrix x4 on f32 data via the b16-pair trick: 8x8 b16 tile == 8 rows x 4 f32
// cols; thread t of each octet gets f32 element (row t/4, col t%4).
DEV_INLINE void ldsm4(uint32_t& r0, uint32_t& r1, uint32_t& r2, uint32_t& r3,
                      uint32_t addr) {
    asm volatile("ldmatrix.sync.aligned.m8n8.x4.shared.b16 {%0,%1,%2,%3}, [%4];"
                 : "=r"(r0), "=r"(r1), "=r"(r2), "=r"(r3) : "r"(addr));
}

DEV_INLINE void cp16(uint32_t smem_addr, const void* gptr) {
    asm volatile("cp.async.cg.shared.global [%0], [%1], 16;\n"
                 :: "r"(smem_addr), "l"(gptr));
}
DEV_INLINE void cp_commit() { asm volatile("cp.async.commit_group;\n"); }
template <int N> DEV_INLINE void cp_wait() {
    asm volatile("cp.async.wait_group %0;\n" :: "n"(N));
}

// ---------------- kernel 0: pack mask into bits ----------------
// bit=1 => masked. Fully-masked rows are written as all-zero (reference resets them).
__global__ __launch_bounds__(256)
void maskpack_kernel(const float* __restrict__ mask) {
    int row = blockIdx.x;                 // 0 .. B*NQ-1
    __shared__ uint32_t wbuf[SW];
    __shared__ int s_all;
    int tid = threadIdx.x, warp = tid >> 5, lane = tid & 31;
    if (tid == 0) s_all = 1;
    __syncthreads();
    const float* mp = mask + (size_t)row * S;
    int myall = 1;
    constexpr int WPW = SW / 8;           // 64 words per warp
    for (int i = 0; i < WPW; i++) {
        int word = warp * WPW + i;
        float v = mp[word * 32 + lane];
        uint32_t bits = __ballot_sync(0xffffffffu, v < 0.5f);
        if (lane == 0) wbuf[word] = bits;
        myall &= (bits == 0xffffffffu);
    }
    if (!myall) s_all = 0;                // benign race
    __syncthreads();
    uint32_t* out = g_mbits + (size_t)row * SW;
    int all = s_all;
    for (int w = tid; w < SW; w += blockDim.x) out[w] = all ? 0u : wbuf[w];
}

// ---------------- TF32 GEMM: C[M,256] = alpha*(A @ W^T + bias) ----------------
// (structure identical to the Round-7 passing kernel; epilogue gains a
//  tfout flag that rounds outputs to tf32 before storing — same layout)
// BM=128, BN=128, BK=32, 2-stage cp.async, ldmatrix fragments.
constexpr int AST = 36;                               // smem row stride (floats)
constexpr int GEMM_SMEM_BYTES = 2 * (128 + 128) * AST * 4;   // 73728
constexpr int NKT = E / 32;                           // 8 k-tiles

__global__ __launch_bounds__(256, 2)
void gemm_tf32_kernel(const float* __restrict__ A, const float* __restrict__ W,
                      const float* __restrict__ bias, float* __restrict__ C,
                      float alpha, int tfout) {
    extern __shared__ float smem[];
    const int tid = threadIdx.x, warp = tid >> 5, lane = tid & 31;
    const int wm = warp >> 1, wn = warp & 1;
    const int m0 = blockIdx.x * 128, n0 = blockIdx.y * 128;
    const int mnum = lane >> 3, rinm = lane & 7;

    // ldmatrix lane geometry
    const int a_row0 = wm * 32 + (mnum & 1) * 8 + rinm;   // + mt*16
    const int a_colb = (mnum >> 1) * 4;
    const int b_row0 = wn * 64 + (mnum >> 1) * 8 + rinm;  // + p*16
    const int b_colb = (mnum & 1) * 4;

    const uint32_t sbase = (uint32_t)__cvta_generic_to_shared(smem);
    constexpr uint32_t STAGE = (128 + 128) * AST * 4;

    float acc[2][8][4];
#pragma unroll
    for (int a = 0; a < 2; a++)
#pragma unroll
        for (int b = 0; b < 8; b++)
#pragma unroll
            for (int c = 0; c < 4; c++) acc[a][b][c] = 0.f;

    auto load_stage = [&](int kt, int s) {
        const float* Ab = A + (size_t)m0 * E + kt * 32;
        const float* Wb = W + (size_t)n0 * E + kt * 32;
        uint32_t as = sbase + s * STAGE;
        uint32_t ws = as + 128 * AST * 4;
#pragma unroll
        for (int i = 0; i < 4; i++) {                 // A: 128x32 = 1024 float4
            int idx = i * 256 + tid;
            int r = idx >> 3, c = (idx & 7) * 4;
            cp16(as + (r * AST + c) * 4, Ab + (size_t)r * E + c);
        }
#pragma unroll
        for (int i = 0; i < 4; i++) {                 // W: 128x32 = 1024 float4
            int idx = i * 256 + tid;
            int r = idx >> 3, c = (idx & 7) * 4;
            cp16(ws + (r * AST + c) * 4, Wb + (size_t)r * E + c);
        }
    };

    load_stage(0, 0); cp_commit();

    for (int kt = 0; kt < NKT; kt++) {
        if (kt + 1 < NKT) { load_stage(kt + 1, (kt + 1) & 1); cp_commit(); cp_wait<1>(); }
        else              { cp_wait<0>(); }
        __syncthreads();

        uint32_t as = sbase + (kt & 1) * STAGE;
        uint32_t ws = as + 128 * AST * 4;
#pragma unroll
        for (int kk = 0; kk < 4; kk++) {
            const int k8 = kk * 8;
            uint32_t a[2][4], bf[4][4];
#pragma unroll
            for (int mt = 0; mt < 2; mt++)
                ldsm4(a[mt][0], a[mt][1], a[mt][2], a[mt][3],
                      as + ((a_row0 + mt * 16) * AST + k8 + a_colb) * 4);
#pragma unroll
            for (int p = 0; p < 4; p++)
                ldsm4(bf[p][0], bf[p][1], bf[p][2], bf[p][3],
                      ws + ((b_row0 + p * 16) * AST + k8 + b_colb) * 4);
#pragma unroll
            for (int mt = 0; mt < 2; mt++)
#pragma unroll
                for (int j = 0; j < 4; j++) a[mt][j] = raw2tf(a[mt][j]);
#pragma unroll
            for (int p = 0; p < 4; p++)
#pragma unroll
                for (int j = 0; j < 4; j++) bf[p][j] = raw2tf(bf[p][j]);
#pragma unroll
            for (int mt = 0; mt < 2; mt++)
#pragma unroll
                for (int p = 0; p < 4; p++) {
                    mma8(acc[mt][2 * p],     a[mt], bf[p][0], bf[p][1]);
                    mma8(acc[mt][2 * p + 1], a[mt], bf[p][2], bf[p][3]);
                }
        }
        __syncthreads();
    }

    // epilogue
    const int g = lane >> 2, tg = lane & 3;
#pragma unroll
    for (int mt = 0; mt < 2; mt++) {
        int r = m0 + wm * 32 + mt * 16 + g;
#pragma unroll
        for (int nt = 0; nt < 8; nt++) {
            int c = n0 + wn * 64 + nt * 8 + 2 * tg;
            float b0v = bias[c], b1v = bias[c + 1];
            float v0 = alpha * (acc[mt][nt][0] + b0v);
            float v1 = alpha * (acc[mt][nt][1] + b1v);
            float v2 = alpha * (acc[mt][nt][2] + b0v);
            float v3 = alpha * (acc[mt][nt][3] + b1v);
            if (tfout) { v0 = f2tff(v0); v1 = f2tff(v1); v2 = f2tff(v2); v3 = f2tff(v3); }
            *(float2*)(C + (size_t)r * E + c)       = make_float2(v0, v1);
            *(float2*)(C + (size_t)(r + 8) * E + c) = make_float2(v2, v3);
        }
    }
}

// ---------------- attention kernel (flash-style, split over S) ----------------
// Structure identical to the Round-4/7 passing version. K and V arrive already
// tf32-rounded from the projection epilogues, so the per-tile cvts are gone.
constexpr int KST = 36, VST = 40, PST = 68;
constexpr int ATTN_SMEM_BYTES = (2 * SKT * KST + 2 * SKT * VST + NQ * PST) * 4;

__global__ __launch_bounds__(256)
void attn_kernel() {
    extern __shared__ float smem[];
    float* Vbuf = smem + 2 * SKT * KST;
    float* Ps   = Vbuf + 2 * SKT * VST;

    const int split = blockIdx.x, h = blockIdx.y, b = blockIdx.z;
    const int tid = threadIdx.x, warp = tid >> 5, lane = tid & 31;
    const int g = lane >> 2, tg = lane & 3;
    const int mnum = lane >> 3, rinm = lane & 7;

    const uint32_t sbase = (uint32_t)__cvta_generic_to_shared(smem);
    const uint32_t kba = sbase;
    const uint32_t vba = sbase + 2 * SKT * KST * 4;
    const uint32_t pba = vba + 2 * SKT * VST * 4;

    const int r0 = warp * 16 + g, r1 = r0 + 8;

    // hoist Q fragments into registers (loop-invariant)
    uint32_t qf[4][4];
    {
        const float* q0 = g_q + (size_t)(b * NQ + r0) * E + h * DH;
        const float* q1 = g_q + (size_t)(b * NQ + r1) * E + h * DH;
#pragma unroll
        for (int kk = 0; kk < 4; kk++) {
            qf[kk][0] = f2tf(q0[kk * 8 + tg]);
            qf[kk][1] = f2tf(q1[kk * 8 + tg]);
            qf[kk][2] = f2tf(q0[kk * 8 + tg + 4]);
            qf[kk][3] = f2tf(q1[kk * 8 + tg + 4]);
        }
    }

    const uint32_t* mw0 = g_mbits + (size_t)(b * NQ + r0) * SW;
    const uint32_t* mw1 = g_mbits + (size_t)(b * NQ + r1) * SW;
    const float* kbase = g_k + (size_t)b * S * E + h * DH;
    const float* vbase = g_v + (size_t)b * S * E + h * DH;
    const int sstart = split * SCHUNK;

    // ldmatrix geometry
    const int k_row  = (mnum >> 1) * 8 + rinm;            // + p*16 (K as B operand)
    const int k_colb = (mnum & 1) * 4;
    const int p_row  = warp * 16 + (mnum & 1) * 8 + rinm; // P as A operand
    const int p_colb = (mnum >> 1) * 4;

    float m0v = NEG, m1v = NEG, l0 = 0.f, l1 = 0.f;
    float o[4][4];
#pragma unroll
    for (int i = 0; i < 4; i++)
#pragma unroll
        for (int j = 0; j < 4; j++) o[i][j] = 0.f;

    auto load_kv = [&](int t, int s) {
        const float* kb = kbase + (size_t)(sstart + t * SKT) * E;
        const float* vb = vbase + (size_t)(sstart + t * SKT) * E;
        uint32_t ka = kba + s * SKT * KST * 4;
        uint32_t va = vba + s * SKT * VST * 4;
#pragma unroll
        for (int i = 0; i < 2; i++) {             // 64x32 = 512 float4 each
            int idx = i * 256 + tid;
            int r = idx >> 3, c = (idx & 7) * 4;
            cp16(ka + (r * KST + c) * 4, kb + (size_t)r * E + c);
            cp16(va + (r * VST + c) * 4, vb + (size_t)r * E + c);
        }
    };

    load_kv(0, 0); cp_commit();

    for (int t = 0; t < NT; t++) {
        if (t + 1 < NT) { load_kv(t + 1, (t + 1) & 1); cp_commit(); cp_wait<1>(); }
        else            { cp_wait<0>(); }
        __syncthreads();

        const int s0 = sstart + t * SKT;
        const uint32_t ka = kba + (t & 1) * SKT * KST * 4;
        const float* Vp = Vbuf + (t & 1) * SKT * VST;

        // scores S_tile[16 x 64] per warp (K pre-tf32: no cvt)
        float sc[8][4];
#pragma unroll
        for (int n = 0; n < 8; n++)
#pragma unroll
            for (int j = 0; j < 4; j++) sc[n][j] = 0.f;

#pragma unroll
        for (int kk = 0; kk < 4; kk++) {
            const int k8 = kk * 8;
#pragma unroll
            for (int p = 0; p < 4; p++) {
                uint32_t br[4];
                ldsm4(br[0], br[1], br[2], br[3],
                      ka + ((k_row + p * 16) * KST + k8 + k_colb) * 4);
                mma8(sc[2 * p],     qf[kk], br[0], br[1]);
                mma8(sc[2 * p + 1], qf[kk], br[2], br[3]);
            }
        }

        // mask (bit=1 => disallowed) + row max
        uint2 w0 = *(const uint2*)(mw0 + (s0 >> 5));
        uint2 w1 = *(const uint2*)(mw1 + (s0 >> 5));
        uint64_t bm0 = (uint64_t)w0.x | ((uint64_t)w0.y << 32);
        uint64_t bm1 = (uint64_t)w1.x | ((uint64_t)w1.y << 32);

        float tm0 = NEG, tm1 = NEG;
#pragma unroll
        for (int n = 0; n < 8; n++) {
            int c = n * 8 + 2 * tg;
            if ((bm0 >> c) & 1)       sc[n][0] = NEG;
            if ((bm0 >> (c + 1)) & 1) sc[n][1] = NEG;
            if ((bm1 >> c) & 1)       sc[n][2] = NEG;
            if ((bm1 >> (c + 1)) & 1) sc[n][3] = NEG;
            tm0 = fmaxf(tm0, fmaxf(sc[n][0], sc[n][1]));
            tm1 = fmaxf(tm1, fmaxf(sc[n][2], sc[n][3]));
        }
        tm0 = fmaxf(tm0, __shfl_xor_sync(0xffffffffu, tm0, 1));
        tm0 = fmaxf(tm0, __shfl_xor_sync(0xffffffffu, tm0, 2));
        tm1 = fmaxf(tm1, __shfl_xor_sync(0xffffffffu, tm1, 1));
        tm1 = fmaxf(tm1, __shfl_xor_sync(0xffffffffu, tm1, 2));

        float mn0 = fmaxf(m0v, tm0), mn1 = fmaxf(m1v, tm1);
        float cf0 = __expf(m0v - mn0), cf1 = __expf(m1v - mn1);

        float rs0 = 0.f, rs1 = 0.f;
#pragma unroll
        for (int n = 0; n < 8; n++) {
            float p0 = __expf(sc[n][0] - mn0);
            float p1 = __expf(sc[n][1] - mn0);
            float p2 = __expf(sc[n][2] - mn1);
            float p3 = __expf(sc[n][3] - mn1);
            rs0 += p0 + p1;
            rs1 += p2 + p3;
            int c = n * 8 + 2 * tg;
            Ps[r0 * PST + c]     = f2tff(p0);
            Ps[r0 * PST + c + 1] = f2tff(p1);
            Ps[r1 * PST + c]     = f2tff(p2);
            Ps[r1 * PST + c + 1] = f2tff(p3);
        }
        rs0 += __shfl_xor_sync(0xffffffffu, rs0, 1);
        rs0 += __shfl_xor_sync(0xffffffffu, rs0, 2);
        rs1 += __shfl_xor_sync(0xffffffffu, rs1, 1);
        rs1 += __shfl_xor_sync(0xffffffffu, rs1, 2);

        l0 = l0 * cf0 + rs0;
        l1 = l1 * cf1 + rs1;
        m0v = mn0; m1v = mn1;
#pragma unroll
        for (int nt = 0; nt < 4; nt++) {
            o[nt][0] *= cf0; o[nt][1] *= cf0;
            o[nt][2] *= cf1; o[nt][3] *= cf1;
        }
        __syncwarp();

        // O += P[16 x 64] @ V[64 x 32]  (V pre-tf32: no cvt, raw bit loads)
#pragma unroll
        for (int kk = 0; kk < 8; kk++) {
            const int k8 = kk * 8;
            uint32_t pa[4];
            ldsm4(pa[0], pa[1], pa[2], pa[3],
                  pba + (p_row * PST + k8 + p_colb) * 4);   // already tf32
#pragma unroll
            for (int nt = 0; nt < 4; nt++) {
                uint32_t b0 = __float_as_uint(Vp[(k8 + tg) * VST + nt * 8 + g]);
                uint32_t b1 = __float_as_uint(Vp[(k8 + tg + 4) * VST + nt * 8 + g]);
                mma8(o[nt], pa, b0, b1);
            }
        }
        __syncwarp();
        __syncthreads();   // before K/V buffers are overwritten
    }

    // write partials (unnormalized)
    size_t pbase = (size_t)((b * H + h) * SPLITS + split) * NQ;
#pragma unroll
    for (int nt = 0; nt < 4; nt++) {
        int c = nt * 8 + 2 * tg;
        *(float2*)(g_po + (pbase + r0) * DH + c) = make_float2(o[nt][0], o[nt][1]);
        *(float2*)(g_po + (pbase + r1) * DH + c) = make_float2(o[nt][2], o[nt][3]);
    }
    if (tg == 0) {
        g_pm[pbase + r0] = m0v; g_pl[pbase + r0] = l0;
        g_pm[pbase + r1] = m1v; g_pl[pbase + r1] = l1;
    }
}

// ---------------- combine kernel ----------------
__global__ __launch_bounds__(256)
void combine_kernel() {
    int widx = blockIdx.x * (blockDim.x >> 5) + (threadIdx.x >> 5);
    int lane = threadIdx.x & 31;
    if (widx >= B * H * NQ) return;
    int q = widx % NQ;
    int bh = widx / NQ;
    int h = bh % H, b = bh / H;

    size_t base = (size_t)bh * SPLITS * NQ + q;
    float M = NEG;
#pragma unroll
    for (int i = 0; i < SPLITS; i++) M = fmaxf(M, g_pm[base + (size_t)i * NQ]);
    float L = 0.f, acc = 0.f;
#pragma unroll
    for (int i = 0; i < SPLITS; i++) {
        float w = __expf(g_pm[base + (size_t)i * NQ] - M);
        L += w * g_pl[base + (size_t)i * NQ];
        acc += w * g_po[(base + (size_t)i * NQ) * DH + lane];
    }
    g_attn[(size_t)(b * NQ + q) * E + h * DH + lane] = acc / L;
}

// ---------------- launcher ----------------
extern "C" void kernel_launch(void* const* d_in, const int* in_sizes, int n_in,
                              void* d_out, int out_size) {
    const float* query = (const float*)d_in[0];
    const float* key   = (const float*)d_in[1];
    const float* value = (const float*)d_in[2];
    const float* mask  = (const float*)d_in[3];
    const float* W_in  = (const float*)d_in[4];
    const float* b_in  = (const float*)d_in[5];
    const float* W_out = (const float*)d_in[6];
    const float* b_out = (const float*)d_in[7];
    float* out = (float*)d_out;

    float *p_q, *p_k, *p_v, *p_attn;
    cudaGetSymbolAddress((void**)&p_q, g_q);
    cudaGetSymbolAddress((void**)&p_k, g_k);
    cudaGetSymbolAddress((void**)&p_v, g_v);
    cudaGetSymbolAddress((void**)&p_attn, g_attn);

    cudaFuncSetAttribute(gemm_tf32_kernel, cudaFuncAttributeMaxDynamicSharedMemorySize,
                         GEMM_SMEM_BYTES);
    cudaFuncSetAttribute(attn_kernel, cudaFuncAttributeMaxDynamicSharedMemorySize,
                         ATTN_SMEM_BYTES);

    const float qscale = 1.0f / sqrtf((float)DH);

    // 0) pack mask bits (handles fully-masked-row reset)
    maskpack_kernel<<<B * NQ, 256>>>(mask);

    // 1) Q projection (scaled, plain f32 out; converted at use in attention)
    gemm_tf32_kernel<<<dim3((B * NQ) / 128, E / 128), 256, GEMM_SMEM_BYTES>>>(
        query, W_in, b_in, p_q, qscale, 0);

    // 2) K projection (tf32-rounded out)
    gemm_tf32_kernel<<<dim3((B * S) / 128, E / 128), 256, GEMM_SMEM_BYTES>>>(
        key, W_in + E * E, b_in + E, p_k, 1.0f, 1);

    // 3) V projection (tf32-rounded out)
    gemm_tf32_kernel<<<dim3((B * S) / 128, E / 128), 256, GEMM_SMEM_BYTES>>>(
        value, W_in + 2 * E * E, b_in + 2 * E, p_v, 1.0f, 1);

    // 4) attention (split over S)
    attn_kernel<<<dim3(SPLITS, H, B), 256, ATTN_SMEM_BYTES>>>();

    // 5) combine splits
    combine_kernel<<<(B * H * NQ + 7) / 8, 256>>>();

    // 6) output projection
    gemm_tf32_kernel<<<dim3((B * NQ) / 128, E / 128), 256, GEMM_SMEM_BYTES>>>(
        p_attn, W_out, b_out, out, 1.0f, 0);
}

// round 11
// speedup vs baseline: 1.1812x; 1.0363x over previous
#include <cuda_runtime.h>
#include <math.h>
#include <stdint.h>

// Shapes (fixed by the problem)
constexpr int B  = 4;
constexpr int NQ = 128;
constexpr int S  = 16384;
constexpr int E  = 256;
constexpr int H  = 8;
constexpr int DH = 32;

constexpr int SPLITS = 16;
constexpr int SCHUNK = S / SPLITS;   // 1024
constexpr int SKT    = 64;           // kv tile per inner iteration
constexpr int NT     = SCHUNK / SKT; // 16
constexpr int SW     = S / 32;       // 512 mask words per row

constexpr float NEG = -1e30f;

#define DEV_INLINE __device__ __forceinline__

// ---------------- scratch (static device memory; no allocations) ----------------
__device__ float    g_q[B * NQ * E];                 // projected Q (scaled, f32)
__device__ float    g_k[(size_t)B * S * E];          // projected K (tf32-rounded f32)
__device__ float    g_v[(size_t)B * S * E];          // projected V (tf32-rounded f32)
__device__ float    g_attn[B * NQ * E];
__device__ float    g_po[(size_t)B * H * SPLITS * NQ * DH];
__device__ float    g_pm[B * H * SPLITS * NQ];
__device__ float    g_pl[B * H * SPLITS * NQ];
__device__ uint32_t g_mbits[(size_t)B * NQ * SW];    // bit=1 => masked (disallowed)
__device__ float    g_win[3 * E * E];                // tf32-rounded W_in
__device__ float    g_wout[E * E];                   // tf32-rounded W_out

// ---------------- helpers ----------------
DEV_INLINE uint32_t f2tf(float x) {
    uint32_t u;
    asm("cvt.rna.tf32.f32 %0, %1;" : "=r"(u) : "f"(x));
    return u;
}
DEV_INLINE float f2tff(float x) { return __uint_as_float(f2tf(x)); }
DEV_INLINE uint32_t raw2tf(uint32_t r) { return f2tf(__uint_as_float(r)); }

DEV_INLINE void mma8(float* d, const uint32_t* a, uint32_t b0, uint32_t b1) {
    asm volatile(
        "mma.sync.aligned.m16n8k8.row.col.f32.tf32.tf32.f32 "
        "{%0,%1,%2,%3}, {%4,%5,%6,%7}, {%8,%9}, {%0,%1,%2,%3};\n"
        : "+f"(d[0]), "+f"(d[1]), "+f"(d[2]), "+f"(d[3])
        : "r"(a[0]), "r"(a[1]), "r"(a[2]), "r"(a[3]), "r"(b0), "r"(b1));
}

// ldmatrix x4 on f32 data via the b16-pair trick: 8x8 b16 tile == 8 rows x 4 f32
// cols; thread t of each octet gets f32 element (row t/4, col t%4).
DEV_INLINE void ldsm4(uint32_t& r0, uint32_t& r1, uint32_t& r2, uint32_t& r3,
                      uint32_t addr) {
    asm volatile("ldmatrix.sync.aligned.m8n8.x4.shared.b16 {%0,%1,%2,%3}, [%4];"
                 : "=r"(r0), "=r"(r1), "=r"(r2), "=r"(r3) : "r"(addr));
}

DEV_INLINE void cp16(uint32_t smem_addr, const void* gptr) {
    asm volatile("cp.async.cg.shared.global [%0], [%1], 16;\n"
                 :: "r"(smem_addr), "l"(gptr));
}
DEV_INLINE void cp_commit() { asm volatile("cp.async.commit_group;\n"); }
template <int N> DEV_INLINE void cp_wait() {
    asm volatile("cp.async.wait_group %0;\n" :: "n"(N));
}

// ---------------- kernel -1: pre-round weights to tf32 (bitwise = in-loop cvt) ----
__global__ __launch_bounds__(256)
void preround_kernel(const float* __restrict__ src, float* __restrict__ dst, int n4) {
    int i = blockIdx.x * 256 + threadIdx.x;
    if (i >= n4) return;
    float4 v = ((const float4*)src)[i];
    v.x = f2tff(v.x); v.y = f2tff(v.y); v.z = f2tff(v.z); v.w = f2tff(v.w);
    ((float4*)dst)[i] = v;
}

// ---------------- kernel 0: pack mask into bits ----------------
// bit=1 => masked. Fully-masked rows are written as all-zero (reference resets them).
__global__ __launch_bounds__(256)
void maskpack_kernel(const float* __restrict__ mask) {
    int row = blockIdx.x;                 // 0 .. B*NQ-1
    __shared__ uint32_t wbuf[SW];
    __shared__ int s_all;
    int tid = threadIdx.x, warp = tid >> 5, lane = tid & 31;
    if (tid == 0) s_all = 1;
    __syncthreads();
    const float* mp = mask + (size_t)row * S;
    int myall = 1;
    constexpr int WPW = SW / 8;           // 64 words per warp
    for (int i = 0; i < WPW; i++) {
        int word = warp * WPW + i;
        float v = mp[word * 32 + lane];
        uint32_t bits = __ballot_sync(0xffffffffu, v < 0.5f);
        if (lane == 0) wbuf[word] = bits;
        myall &= (bits == 0xffffffffu);
    }
    if (!myall) s_all = 0;                // benign race
    __syncthreads();
    uint32_t* out = g_mbits + (size_t)row * SW;
    int all = s_all;
    for (int w = tid; w < SW; w += blockDim.x) out[w] = all ? 0u : wbuf[w];
}

// ---------------- TF32 GEMM: C[M,256] = alpha*(A @ W^T + bias) ----------------
// W arrives PRE-ROUNDED to tf32 (g_win/g_wout) -> no cvt on the B operand.
// BM=128, BN=128, BK=32, 2-stage cp.async, ldmatrix fragments. 8 warps 4mx2n.
constexpr int AST = 36;                               // smem row stride (floats)
constexpr int GEMM_SMEM_BYTES = 2 * (128 + 128) * AST * 4;   // 73728
constexpr int NKT = E / 32;                           // 8 k-tiles

__global__ __launch_bounds__(256, 2)
void gemm_tf32_kernel(const float* __restrict__ A, const float* __restrict__ W,
                      const float* __restrict__ bias, float* __restrict__ C,
                      float alpha, int tfout) {
    extern __shared__ float smem[];
    const int tid = threadIdx.x, warp = tid >> 5, lane = tid & 31;
    const int wm = warp >> 1, wn = warp & 1;
    const int m0 = blockIdx.x * 128, n0 = blockIdx.y * 128;
    const int mnum = lane >> 3, rinm = lane & 7;

    // ldmatrix lane geometry
    const int a_row0 = wm * 32 + (mnum & 1) * 8 + rinm;   // + mt*16
    const int a_colb = (mnum >> 1) * 4;
    const int b_row0 = wn * 64 + (mnum >> 1) * 8 + rinm;  // + p*16
    const int b_colb = (mnum & 1) * 4;

    const uint32_t sbase = (uint32_t)__cvta_generic_to_shared(smem);
    constexpr uint32_t STAGE = (128 + 128) * AST * 4;

    float acc[2][8][4];
#pragma unroll
    for (int a = 0; a < 2; a++)
#pragma unroll
        for (int b = 0; b < 8; b++)
#pragma unroll
            for (int c = 0; c < 4; c++) acc[a][b][c] = 0.f;

    auto load_stage = [&](int kt, int s) {
        const float* Ab = A + (size_t)m0 * E + kt * 32;
        const float* Wb = W + (size_t)n0 * E + kt * 32;
        uint32_t as = sbase + s * STAGE;
        uint32_t ws = as + 128 * AST * 4;
#pragma unroll
        for (int i = 0; i < 4; i++) {                 // A: 128x32 = 1024 float4
            int idx = i * 256 + tid;
            int r = idx >> 3, c = (idx & 7) * 4;
            cp16(as + (r * AST + c) * 4, Ab + (size_t)r * E + c);
        }
#pragma unroll
        for (int i = 0; i < 4; i++) {                 // W: 128x32 = 1024 float4
            int idx = i * 256 + tid;
            int r = idx >> 3, c = (idx & 7) * 4;
            cp16(ws + (r * AST + c) * 4, Wb + (size_t)r * E + c);
        }
    };

    load_stage(0, 0); cp_commit();

    for (int kt = 0; kt < NKT; kt++) {
        if (kt + 1 < NKT) { load_stage(kt + 1, (kt + 1) & 1); cp_commit(); cp_wait<1>(); }
        else              { cp_wait<0>(); }
        __syncthreads();

        uint32_t as = sbase + (kt & 1) * STAGE;
        uint32_t ws = as + 128 * AST * 4;
#pragma unroll
        for (int kk = 0; kk < 4; kk++) {
            const int k8 = kk * 8;
            uint32_t a[2][4], bf[4][4];
#pragma unroll
            for (int mt = 0; mt < 2; mt++)
                ldsm4(a[mt][0], a[mt][1], a[mt][2], a[mt][3],
                      as + ((a_row0 + mt * 16) * AST + k8 + a_colb) * 4);
#pragma unroll
            for (int p = 0; p < 4; p++)
                ldsm4(bf[p][0], bf[p][1], bf[p][2], bf[p][3],
                      ws + ((b_row0 + p * 16) * AST + k8 + b_colb) * 4);
            // A operand: raw f32 -> cvt.  B operand: pre-rounded -> use bits directly.
#pragma unroll
            for (int mt = 0; mt < 2; mt++)
#pragma unroll
                for (int j = 0; j < 4; j++) a[mt][j] = raw2tf(a[mt][j]);
#pragma unroll
            for (int mt = 0; mt < 2; mt++)
#pragma unroll
                for (int p = 0; p < 4; p++) {
                    mma8(acc[mt][2 * p],     a[mt], bf[p][0], bf[p][1]);
                    mma8(acc[mt][2 * p + 1], a[mt], bf[p][2], bf[p][3]);
                }
        }
        __syncthreads();
    }

    // epilogue
    const int g = lane >> 2, tg = lane & 3;
#pragma unroll
    for (int mt = 0; mt < 2; mt++) {
        int r = m0 + wm * 32 + mt * 16 + g;
#pragma unroll
        for (int nt = 0; nt < 8; nt++) {
            int c = n0 + wn * 64 + nt * 8 + 2 * tg;
            float b0v = bias[c], b1v = bias[c + 1];
            float v0 = alpha * (acc[mt][nt][0] + b0v);
            float v1 = alpha * (acc[mt][nt][1] + b1v);
            float v2 = alpha * (acc[mt][nt][2] + b0v);
            float v3 = alpha * (acc[mt][nt][3] + b1v);
            if (tfout) { v0 = f2tff(v0); v1 = f2tff(v1); v2 = f2tff(v2); v3 = f2tff(v3); }
            *(float2*)(C + (size_t)r * E + c)       = make_float2(v0, v1);
            *(float2*)(C + (size_t)(r + 8) * E + c) = make_float2(v2, v3);
        }
    }
}

// ---------------- attention kernel (flash-style, split over S) ----------------
// (byte-identical to the Round-10 passing version)
constexpr int KST = 36, VST = 40, PST = 68;
constexpr int ATTN_SMEM_BYTES = (2 * SKT * KST + 2 * SKT * VST + NQ * PST) * 4;

__global__ __launch_bounds__(256)
void attn_kernel() {
    extern __shared__ float smem[];
    float* Vbuf = smem + 2 * SKT * KST;
    float* Ps   = Vbuf + 2 * SKT * VST;

    const int split = blockIdx.x, h = blockIdx.y, b = blockIdx.z;
    const int tid = threadIdx.x, warp = tid >> 5, lane = tid & 31;
    const int g = lane >> 2, tg = lane & 3;
    const int mnum = lane >> 3, rinm = lane & 7;

    const uint32_t sbase = (uint32_t)__cvta_generic_to_shared(smem);
    const uint32_t kba = sbase;
    const uint32_t vba = sbase + 2 * SKT * KST * 4;
    const uint32_t pba = vba + 2 * SKT * VST * 4;

    const int r0 = warp * 16 + g, r1 = r0 + 8;

    // hoist Q fragments into registers (loop-invariant)
    uint32_t qf[4][4];
    {
        const float* q0 = g_q + (size_t)(b * NQ + r0) * E + h * DH;
        const float* q1 = g_q + (size_t)(b * NQ + r1) * E + h * DH;
#pragma unroll
        for (int kk = 0; kk < 4; kk++) {
            qf[kk][0] = f2tf(q0[kk * 8 + tg]);
            qf[kk][1] = f2tf(q1[kk * 8 + tg]);
            qf[kk][2] = f2tf(q0[kk * 8 + tg + 4]);
            qf[kk][3] = f2tf(q1[kk * 8 + tg + 4]);
        }
    }

    const uint32_t* mw0 = g_mbits + (size_t)(b * NQ + r0) * SW;
    const uint32_t* mw1 = g_mbits + (size_t)(b * NQ + r1) * SW;
    const float* kbase = g_k + (size_t)b * S * E + h * DH;
    const float* vbase = g_v + (size_t)b * S * E + h * DH;
    const int sstart = split * SCHUNK;

    // ldmatrix geometry
    const int k_row  = (mnum >> 1) * 8 + rinm;            // + p*16 (K as B operand)
    const int k_colb = (mnum & 1) * 4;
    const int p_row  = warp * 16 + (mnum & 1) * 8 + rinm; // P as A operand
    const int p_colb = (mnum >> 1) * 4;

    float m0v = NEG, m1v = NEG, l0 = 0.f, l1 = 0.f;
    float o[4][4];
#pragma unroll
    for (int i = 0; i < 4; i++)
#pragma unroll
        for (int j = 0; j < 4; j++) o[i][j] = 0.f;

    auto load_kv = [&](int t, int s) {
        const float* kb = kbase + (size_t)(sstart + t * SKT) * E;
        const float* vb = vbase + (size_t)(sstart + t * SKT) * E;
        uint32_t ka = kba + s * SKT * KST * 4;
        uint32_t va = vba + s * SKT * VST * 4;
#pragma unroll
        for (int i = 0; i < 2; i++) {             // 64x32 = 512 float4 each
            int idx = i * 256 + tid;
            int r = idx >> 3, c = (idx & 7) * 4;
            cp16(ka + (r * KST + c) * 4, kb + (size_t)r * E + c);
            cp16(va + (r * VST + c) * 4, vb + (size_t)r * E + c);
        }
    };

    load_kv(0, 0); cp_commit();

    for (int t = 0; t < NT; t++) {
        if (t + 1 < NT) { load_kv(t + 1, (t + 1) & 1); cp_commit(); cp_wait<1>(); }
        else            { cp_wait<0>(); }
        __syncthreads();

        const int s0 = sstart + t * SKT;
        const uint32_t ka = kba + (t & 1) * SKT * KST * 4;
        const float* Vp = Vbuf + (t & 1) * SKT * VST;

        // scores S_tile[16 x 64] per warp (K pre-tf32: no cvt)
        float sc[8][4];
#pragma unroll
        for (int n = 0; n < 8; n++)
#pragma unroll
            for (int j = 0; j < 4; j++) sc[n][j] = 0.f;

#pragma unroll
        for (int kk = 0; kk < 4; kk++) {
            const int k8 = kk * 8;
#pragma unroll
            for (int p = 0; p < 4; p++) {
                uint32_t br[4];
                ldsm4(br[0], br[1], br[2], br[3],
                      ka + ((k_row + p * 16) * KST + k8 + k_colb) * 4);
                mma8(sc[2 * p],     qf[kk], br[0], br[1]);
                mma8(sc[2 * p + 1], qf[kk], br[2], br[3]);
            }
        }

        // mask (bit=1 => disallowed) + row max
        uint2 w0 = *(const uint2*)(mw0 + (s0 >> 5));
        uint2 w1 = *(const uint2*)(mw1 + (s0 >> 5));
        uint64_t bm0 = (uint64_t)w0.x | ((uint64_t)w0.y << 32);
        uint64_t bm1 = (uint64_t)w1.x | ((uint64_t)w1.y << 32);

        float tm0 = NEG, tm1 = NEG;
#pragma unroll
        for (int n = 0; n < 8; n++) {
            int c = n * 8 + 2 * tg;
            if ((bm0 >> c) & 1)       sc[n][0] = NEG;
            if ((bm0 >> (c + 1)) & 1) sc[n][1] = NEG;
            if ((bm1 >> c) & 1)       sc[n][2] = NEG;
            if ((bm1 >> (c + 1)) & 1) sc[n][3] = NEG;
            tm0 = fmaxf(tm0, fmaxf(sc[n][0], sc[n][1]));
            tm1 = fmaxf(tm1, fmaxf(sc[n][2], sc[n][3]));
        }
        tm0 = fmaxf(tm0, __shfl_xor_sync(0xffffffffu, tm0, 1));
        tm0 = fmaxf(tm0, __shfl_xor_sync(0xffffffffu, tm0, 2));
        tm1 = fmaxf(tm1, __shfl_xor_sync(0xffffffffu, tm1, 1));
        tm1 = fmaxf(tm1, __shfl_xor_sync(0xffffffffu, tm1, 2));

        float mn0 = fmaxf(m0v, tm0), mn1 = fmaxf(m1v, tm1);
        float cf0 = __expf(m0v - mn0), cf1 = __expf(m1v - mn1);

        float rs0 = 0.f, rs1 = 0.f;
#pragma unroll
        for (int n = 0; n < 8; n++) {
            float p0 = __expf(sc[n][0] - mn0);
            float p1 = __expf(sc[n][1] - mn0);
            float p2 = __expf(sc[n][2] - mn1);
            float p3 = __expf(sc[n][3] - mn1);
            rs0 += p0 + p1;
            rs1 += p2 + p3;
            int c = n * 8 + 2 * tg;
            Ps[r0 * PST + c]     = f2tff(p0);
            Ps[r0 * PST + c + 1] = f2tff(p1);
            Ps[r1 * PST + c]     = f2tff(p2);
            Ps[r1 * PST + c + 1] = f2tff(p3);
        }
        rs0 += __shfl_xor_sync(0xffffffffu, rs0, 1);
        rs0 += __shfl_xor_sync(0xffffffffu, rs0, 2);
        rs1 += __shfl_xor_sync(0xffffffffu, rs1, 1);
        rs1 += __shfl_xor_sync(0xffffffffu, rs1, 2);

        l0 = l0 * cf0 + rs0;
        l1 = l1 * cf1 + rs1;
        m0v = mn0; m1v = mn1;
#pragma unroll
        for (int nt = 0; nt < 4; nt++) {
            o[nt][0] *= cf0; o[nt][1] *= cf0;
            o[nt][2] *= cf1; o[nt][3] *= cf1;
        }
        __syncwarp();

        // O += P[16 x 64] @ V[64 x 32]  (V pre-tf32: no cvt, raw bit loads)
#pragma unroll
        for (int kk = 0; kk < 8; kk++) {
            const int k8 = kk * 8;
            uint32_t pa[4];
            ldsm4(pa[0], pa[1], pa[2], pa[3],
                  pba + (p_row * PST + k8 + p_colb) * 4);   // already tf32
#pragma unroll
            for (int nt = 0; nt < 4; nt++) {
                uint32_t b0 = __float_as_uint(Vp[(k8 + tg) * VST + nt * 8 + g]);
                uint32_t b1 = __float_as_uint(Vp[(k8 + tg + 4) * VST + nt * 8 + g]);
                mma8(o[nt], pa, b0, b1);
            }
        }
        __syncwarp();
        __syncthreads();   // before K/V buffers are overwritten
    }

    // write partials (unnormalized)
    size_t pbase = (size_t)((b * H + h) * SPLITS + split) * NQ;
#pragma unroll
    for (int nt = 0; nt < 4; nt++) {
        int c = nt * 8 + 2 * tg;
        *(float2*)(g_po + (pbase + r0) * DH + c) = make_float2(o[nt][0], o[nt][1]);
        *(float2*)(g_po + (pbase + r1) * DH + c) = make_float2(o[nt][2], o[nt][3]);
    }
    if (tg == 0) {
        g_pm[pbase + r0] = m0v; g_pl[pbase + r0] = l0;
        g_pm[pbase + r1] = m1v; g_pl[pbase + r1] = l1;
    }
}

// ---------------- combine kernel ----------------
__global__ __launch_bounds__(256)
void combine_kernel() {
    int widx = blockIdx.x * (blockDim.x >> 5) + (threadIdx.x >> 5);
    int lane = threadIdx.x & 31;
    if (widx >= B * H * NQ) return;
    int q = widx % NQ;
    int bh = widx / NQ;
    int h = bh % H, b = bh / H;

    size_t base = (size_t)bh * SPLITS * NQ + q;
    float M = NEG;
#pragma unroll
    for (int i = 0; i < SPLITS; i++) M = fmaxf(M, g_pm[base + (size_t)i * NQ]);
    float L = 0.f, acc = 0.f;
#pragma unroll
    for (int i = 0; i < SPLITS; i++) {
        float w = __expf(g_pm[base + (size_t)i * NQ] - M);
        L += w * g_pl[base + (size_t)i * NQ];
        acc += w * g_po[(base + (size_t)i * NQ) * DH + lane];
    }
    g_attn[(size_t)(b * NQ + q) * E + h * DH + lane] = acc / L;
}

// ---------------- launcher ----------------
extern "C" void kernel_launch(void* const* d_in, const int* in_sizes, int n_in,
                              void* d_out, int out_size) {
    const float* query = (const float*)d_in[0];
    const float* key   = (const float*)d_in[1];
    const float* value = (const float*)d_in[2];
    const float* mask  = (const float*)d_in[3];
    const float* W_in  = (const float*)d_in[4];
    const float* b_in  = (const float*)d_in[5];
    const float* W_out = (const float*)d_in[6];
    const float* b_out = (const float*)d_in[7];
    float* out = (float*)d_out;

    float *p_q, *p_k, *p_v, *p_attn, *p_win, *p_wout;
    cudaGetSymbolAddress((void**)&p_q, g_q);
    cudaGetSymbolAddress((void**)&p_k, g_k);
    cudaGetSymbolAddress((void**)&p_v, g_v);
    cudaGetSymbolAddress((void**)&p_attn, g_attn);
    cudaGetSymbolAddress((void**)&p_win, g_win);
    cudaGetSymbolAddress((void**)&p_wout, g_wout);

    cudaFuncSetAttribute(gemm_tf32_kernel, cudaFuncAttributeMaxDynamicSharedMemorySize,
                         GEMM_SMEM_BYTES);
    cudaFuncSetAttribute(attn_kernel, cudaFuncAttributeMaxDynamicSharedMemorySize,
                         ATTN_SMEM_BYTES);

    const float qscale = 1.0f / sqrtf((float)DH);

    // -1) pre-round weights to tf32 (bitwise identical to in-loop cvt)
    preround_kernel<<<(3 * E * E / 4 + 255) / 256, 256>>>(W_in, p_win, 3 * E * E / 4);
    preround_kernel<<<(E * E / 4 + 255) / 256, 256>>>(W_out, p_wout, E * E / 4);

    // 0) pack mask bits (handles fully-masked-row reset)
    maskpack_kernel<<<B * NQ, 256>>>(mask);

    // 1) Q projection (scaled, plain f32 out; converted at use in attention)
    gemm_tf32_kernel<<<dim3((B * NQ) / 128, E / 128), 256, GEMM_SMEM_BYTES>>>(
        query, p_win, b_in, p_q, qscale, 0);

    // 2) K projection (tf32-rounded out)
    gemm_tf32_kernel<<<dim3((B * S) / 128, E / 128), 256, GEMM_SMEM_BYTES>>>(
        key, p_win + E * E, b_in + E, p_k, 1.0f, 1);

    // 3) V projection (tf32-rounded out)
    gemm_tf32_kernel<<<dim3((B * S) / 128, E / 128), 256, GEMM_SMEM_BYTES>>>(
        value, p_win + 2 * E * E, b_in + 2 * E, p_v, 1.0f, 1);

    // 4) attention (split over S)
    attn_kernel<<<dim3(SPLITS, H, B), 256, ATTN_SMEM_BYTES>>>();

    // 5) combine splits
    combine_kernel<<<(B * H * NQ + 7) / 8, 256>>>();

    // 6) output projection
    gemm_tf32_kernel<<<dim3((B * NQ) / 128, E / 128), 256, GEMM_SMEM_BYTES>>>(
        p_attn, p_wout, b_out, out, 1.0f, 0);
}